// round 3
// baseline (speedup 1.0000x reference)
#include <cuda_runtime.h>
#include <cstdint>

#define K_DIM 4096   // inner dim (I)
#define N_DIM 2048   // output channels (O)
#define M_DIM 8192   // batch*seq = 4*2048
#define DGRP 8       // PQ group size
#define KCB 256      // codebook entries

#define BM 128
#define BN 128
#define BK 16
#define PAD 4        // smem padding to avoid bank conflicts on transposed stores

// 32 MB scratch for the dequantized weight matrix [N_DIM, K_DIM] row-major.
__device__ float g_wq[(size_t)N_DIM * K_DIM];

// ---------------------------------------------------------------------------
// Kernel 1: per-row abs-max scale + nearest-codeword quantize + dequantize.
// One block (256 threads) per output row o.
// ---------------------------------------------------------------------------
__global__ __launch_bounds__(256)
void pq_quantize(const float* __restrict__ weight,
                 const float* __restrict__ codebook) {
    __shared__ float cb[KCB * DGRP];     // 8 KB codebook
    __shared__ float cnorm_half[KCB];    // 0.5*||c||^2
    __shared__ float red[256];

    const int o   = blockIdx.x;
    const int tid = threadIdx.x;

    // stage codebook
    for (int i = tid; i < KCB * DGRP; i += 256) cb[i] = codebook[i];
    __syncthreads();
    {
        float s = 0.f;
        #pragma unroll
        for (int j = 0; j < DGRP; j++) {
            float c = cb[tid * DGRP + j];
            s = fmaf(c, c, s);
        }
        cnorm_half[tid] = 0.5f * s;
    }

    // row abs-max
    const float* wrow = weight + (size_t)o * K_DIM;
    float m = 0.f;
    for (int i = tid; i < K_DIM; i += 256) m = fmaxf(m, fabsf(wrow[i]));
    red[tid] = m;
    __syncthreads();
    for (int s = 128; s > 0; s >>= 1) {
        if (tid < s) red[tid] = fmaxf(red[tid], red[tid + s]);
        __syncthreads();
    }
    const float scale = fmaxf(red[0], 1e-6f);
    const float inv   = 1.f / scale;

    // each thread handles 2 groups (512 groups per row)
    float* wq_row = g_wq + (size_t)o * K_DIM;
    for (int g = tid; g < K_DIM / DGRP; g += 256) {
        float gv[DGRP];
        #pragma unroll
        for (int j = 0; j < DGRP; j++) gv[j] = wrow[g * DGRP + j] * inv;

        float best = 3.4e38f;
        int   bi   = 0;
        for (int k = 0; k < KCB; k++) {
            float d = cnorm_half[k];
            #pragma unroll
            for (int j = 0; j < DGRP; j++) d = fmaf(-gv[j], cb[k * DGRP + j], d);
            if (d < best) { best = d; bi = k; }   // strict < keeps first min (matches argmin)
        }
        #pragma unroll
        for (int j = 0; j < DGRP; j++)
            wq_row[g * DGRP + j] = cb[bi * DGRP + j] * scale;
    }
}

// ---------------------------------------------------------------------------
// Kernel 2: out[M, N] = X[M, K] @ Wq^T[K, N] + bias.  All tiles full-size.
// 128x128x16 block tile, 256 threads, 8x8 register micro-tile per thread.
// ---------------------------------------------------------------------------
__global__ __launch_bounds__(256, 2)
void pq_sgemm(const float* __restrict__ X,
              const float* __restrict__ bias,
              float* __restrict__ out) {
    __shared__ float As[BK][BM + PAD];   // transposed: As[k][m]
    __shared__ float Bs[BK][BN + PAD];   // transposed: Bs[k][n]

    const int tid = threadIdx.x;
    const int bm  = blockIdx.y * BM;
    const int bn  = blockIdx.x * BN;

    // global-load mapping: each thread loads 2 float4 of A and 2 float4 of B
    const int lrow = tid >> 2;           // 0..63
    const int lcol = (tid & 3) << 2;     // 0,4,8,12

    const float* Ap = X    + (size_t)(bm + lrow) * K_DIM + lcol;
    const float* Bp = g_wq + (size_t)(bn + lrow) * K_DIM + lcol;

    const int ty = tid >> 4;   // 0..15  (row group)
    const int tx = tid & 15;   // 0..15  (col group)

    float acc[8][8];
    #pragma unroll
    for (int i = 0; i < 8; i++)
        #pragma unroll
        for (int j = 0; j < 8; j++) acc[i][j] = 0.f;

    for (int k0 = 0; k0 < K_DIM; k0 += BK) {
        float4 a0 = *(const float4*)(Ap);
        float4 a1 = *(const float4*)(Ap + (size_t)64 * K_DIM);
        float4 b0 = *(const float4*)(Bp);
        float4 b1 = *(const float4*)(Bp + (size_t)64 * K_DIM);
        Ap += BK; Bp += BK;

        __syncthreads();   // previous tile fully consumed before overwrite
        As[lcol + 0][lrow]      = a0.x;
        As[lcol + 1][lrow]      = a0.y;
        As[lcol + 2][lrow]      = a0.z;
        As[lcol + 3][lrow]      = a0.w;
        As[lcol + 0][lrow + 64] = a1.x;
        As[lcol + 1][lrow + 64] = a1.y;
        As[lcol + 2][lrow + 64] = a1.z;
        As[lcol + 3][lrow + 64] = a1.w;
        Bs[lcol + 0][lrow]      = b0.x;
        Bs[lcol + 1][lrow]      = b0.y;
        Bs[lcol + 2][lrow]      = b0.z;
        Bs[lcol + 3][lrow]      = b0.w;
        Bs[lcol + 0][lrow + 64] = b1.x;
        Bs[lcol + 1][lrow + 64] = b1.y;
        Bs[lcol + 2][lrow + 64] = b1.z;
        Bs[lcol + 3][lrow + 64] = b1.w;
        __syncthreads();

        #pragma unroll
        for (int kk = 0; kk < BK; kk++) {
            float4 af0 = *(const float4*)&As[kk][ty * 8];
            float4 af1 = *(const float4*)&As[kk][ty * 8 + 4];
            float4 bf0 = *(const float4*)&Bs[kk][tx * 8];
            float4 bf1 = *(const float4*)&Bs[kk][tx * 8 + 4];
            float a[8] = {af0.x, af0.y, af0.z, af0.w, af1.x, af1.y, af1.z, af1.w};
            float b[8] = {bf0.x, bf0.y, bf0.z, bf0.w, bf1.x, bf1.y, bf1.z, bf1.w};
            #pragma unroll
            for (int i = 0; i < 8; i++)
                #pragma unroll
                for (int j = 0; j < 8; j++)
                    acc[i][j] = fmaf(a[i], b[j], acc[i][j]);
        }
    }

    // epilogue: add bias, vectorized stores
    const int row0 = bm + ty * 8;
    const int col0 = bn + tx * 8;
    float4 bias0 = *(const float4*)&bias[col0];
    float4 bias1 = *(const float4*)&bias[col0 + 4];
    #pragma unroll
    for (int i = 0; i < 8; i++) {
        float* orow = out + (size_t)(row0 + i) * N_DIM + col0;
        float4 v0, v1;
        v0.x = acc[i][0] + bias0.x;
        v0.y = acc[i][1] + bias0.y;
        v0.z = acc[i][2] + bias0.z;
        v0.w = acc[i][3] + bias0.w;
        v1.x = acc[i][4] + bias1.x;
        v1.y = acc[i][5] + bias1.y;
        v1.z = acc[i][6] + bias1.z;
        v1.w = acc[i][7] + bias1.w;
        *(float4*)(orow)     = v0;
        *(float4*)(orow + 4) = v1;
    }
}

// ---------------------------------------------------------------------------
extern "C" void kernel_launch(void* const* d_in, const int* in_sizes, int n_in,
                              void* d_out, int out_size) {
    const float* x        = (const float*)d_in[0];   // [4, 2048, 4096]
    const float* weight   = (const float*)d_in[1];   // [2048, 4096]
    const float* codebook = (const float*)d_in[2];   // [256, 8]
    const float* bias     = (const float*)d_in[3];   // [2048]
    float* out = (float*)d_out;                      // [4, 2048, 2048]

    pq_quantize<<<N_DIM, 256>>>(weight, codebook);

    dim3 grid(N_DIM / BN, M_DIM / BM);   // (16, 64)
    pq_sgemm<<<grid, 256>>>(x, bias, out);
}

// round 5
// speedup vs baseline: 2.3753x; 2.3753x over previous
#include <cuda_runtime.h>
#include <cuda_bf16.h>
#include <cstdint>

#define K1    4096
#define K2    12288          // 3 concatenated segments
#define N_DIM 2048
#define M_DIM 8192
#define DGRP  8
#define KCB   256

// GEMM tiling
#define BM2    128
#define BN2    256
#define KC     64            // bf16 per stage => 128B rows
#define STAGES 3
#define S_TOT  (K2 / KC)     // 192
#define A_ST   (BM2 * KC * 2)              // 16384
#define B_ST   (BN2 * KC * 2)              // 32768
#define STAGE_BYTES (A_ST + B_ST)          // 49152
#define SMEM_G (STAGES * STAGE_BYTES)      // 147456

__device__ __align__(256) __nv_bfloat16 g_xcat[(size_t)M_DIM * K2];  // [xhi|xlo|xhi]
__device__ __align__(256) __nv_bfloat16 g_wcat[(size_t)N_DIM * K2];  // [whi|whi|wlo]

// ---------------- PTX helpers (base sm_103 target only) ----------------
__device__ __forceinline__ uint32_t smem_u32(const void* p) {
    uint32_t a;
    asm("{ .reg .u64 t; cvta.to.shared.u64 t, %1; cvt.u32.u64 %0, t; }" : "=r"(a) : "l"(p));
    return a;
}
#define CP_ASYNC16(dst, src) \
    asm volatile("cp.async.cg.shared.global [%0], [%1], 16;" :: "r"(dst), "l"(src))
#define CP_COMMIT() asm volatile("cp.async.commit_group;" ::: "memory")
#define CP_WAIT1()  asm volatile("cp.async.wait_group 1;" ::: "memory")

#define LDSM_X4(r0,r1,r2,r3,addr) \
    asm volatile("ldmatrix.sync.aligned.m8n8.x4.shared.b16 {%0,%1,%2,%3}, [%4];" \
                 : "=r"(r0), "=r"(r1), "=r"(r2), "=r"(r3) : "r"(addr))

#define MMA16816(d, a0,a1,a2,a3, b0,b1) \
    asm volatile("mma.sync.aligned.m16n8k16.row.col.f32.bf16.bf16.f32 " \
                 "{%0,%1,%2,%3},{%4,%5,%6,%7},{%8,%9},{%0,%1,%2,%3};" \
                 : "+f"((d)[0]), "+f"((d)[1]), "+f"((d)[2]), "+f"((d)[3]) \
                 : "r"(a0), "r"(a1), "r"(a2), "r"(a3), "r"(b0), "r"(b1))

// ---------------- Kernel 1: quantize weight + bf16 hi/lo split ----------------
__global__ __launch_bounds__(256)
void pq_quantize(const float* __restrict__ weight, const float* __restrict__ codebook) {
    __shared__ float cb[KCB * DGRP];
    __shared__ float cnorm_half[KCB];
    __shared__ float red[256];

    const int o = blockIdx.x, tid = threadIdx.x;
    for (int i = tid; i < KCB * DGRP; i += 256) cb[i] = codebook[i];
    __syncthreads();
    {
        float s = 0.f;
        #pragma unroll
        for (int j = 0; j < DGRP; j++) { float c = cb[tid * DGRP + j]; s = fmaf(c, c, s); }
        cnorm_half[tid] = 0.5f * s;
    }
    const float* wrow = weight + (size_t)o * K1;
    float m = 0.f;
    for (int i = tid; i < K1; i += 256) m = fmaxf(m, fabsf(wrow[i]));
    red[tid] = m;
    __syncthreads();
    for (int s = 128; s > 0; s >>= 1) { if (tid < s) red[tid] = fmaxf(red[tid], red[tid + s]); __syncthreads(); }
    const float scale = fmaxf(red[0], 1e-6f);
    const float inv = 1.f / scale;

    __nv_bfloat16* wr = g_wcat + (size_t)o * K2;
    for (int g = tid; g < K1 / DGRP; g += 256) {
        float gv[DGRP];
        #pragma unroll
        for (int j = 0; j < DGRP; j++) gv[j] = wrow[g * DGRP + j] * inv;
        float best = 3.4e38f; int bi = 0;
        for (int k = 0; k < KCB; k++) {
            float d = cnorm_half[k];
            #pragma unroll
            for (int j = 0; j < DGRP; j++) d = fmaf(-gv[j], cb[k * DGRP + j], d);
            if (d < best) { best = d; bi = k; }
        }
        #pragma unroll
        for (int j = 0; j < DGRP; j++) {
            float w = cb[bi * DGRP + j] * scale;
            __nv_bfloat16 hi = __float2bfloat16(w);
            __nv_bfloat16 lo = __float2bfloat16(w - __bfloat162float(hi));
            int i = g * DGRP + j;
            wr[i] = hi; wr[K1 + i] = hi; wr[2 * K1 + i] = lo;
        }
    }
}

// ---------------- Kernel 2: x -> bf16 hi/lo ----------------
__global__ __launch_bounds__(256)
void x_convert(const float* __restrict__ x) {
    size_t idx = (size_t)blockIdx.x * 256 + threadIdx.x;   // one float4
    float4 v = ((const float4*)x)[idx];
    size_t m = idx >> 10;
    size_t kq = (idx & 1023) << 2;

    __nv_bfloat16 h0 = __float2bfloat16(v.x), h1 = __float2bfloat16(v.y);
    __nv_bfloat16 h2 = __float2bfloat16(v.z), h3 = __float2bfloat16(v.w);
    __nv_bfloat16 l0 = __float2bfloat16(v.x - __bfloat162float(h0));
    __nv_bfloat16 l1 = __float2bfloat16(v.y - __bfloat162float(h1));
    __nv_bfloat16 l2 = __float2bfloat16(v.z - __bfloat162float(h2));
    __nv_bfloat16 l3 = __float2bfloat16(v.w - __bfloat162float(h3));

    union { __nv_bfloat16 b[4]; uint2 u; } ph, pl;
    ph.b[0]=h0; ph.b[1]=h1; ph.b[2]=h2; ph.b[3]=h3;
    pl.b[0]=l0; pl.b[1]=l1; pl.b[2]=l2; pl.b[3]=l3;

    size_t base = m * K2 + kq;
    *(uint2*)(g_xcat + base)          = ph.u;
    *(uint2*)(g_xcat + base + K1)     = pl.u;
    *(uint2*)(g_xcat + base + 2*K1)   = ph.u;
}

// ---------------- Kernel 3: bf16 HMMA GEMM, 128x256 CTA, 3-stage cp.async ----------------
__global__ __launch_bounds__(512, 1)
void pq_gemm_mma(const float* __restrict__ bias, float* __restrict__ out) {
    extern __shared__ char smem[];
    const uint32_t sbase = smem_u32(smem);
    const int tid  = threadIdx.x;
    const int wid  = tid >> 5;
    const int lane = tid & 31;

    const size_t m0 = (size_t)blockIdx.y * BM2;
    const size_t n0 = (size_t)blockIdx.x * BN2;
    const size_t gstride = (size_t)K2 * 2;   // row bytes

    // --- cp.async chunk mapping: A 1024 chunks (2/thread), B 2048 (4/thread)
    const char* ga[2]; uint32_t da[2];
    #pragma unroll
    for (int i = 0; i < 2; i++) {
        int c = tid + 512 * i, row = c >> 3, ci = c & 7;
        ga[i] = (const char*)g_xcat + (m0 + row) * gstride + ci * 16;
        da[i] = (uint32_t)(row * 128 + ((ci * 16) ^ ((row & 7) << 4)));
    }
    const char* gb[4]; uint32_t db[4];
    #pragma unroll
    for (int i = 0; i < 4; i++) {
        int c = tid + 512 * i, row = c >> 3, ci = c & 7;
        gb[i] = (const char*)g_wcat + (n0 + row) * gstride + ci * 16;
        db[i] = (uint32_t)(A_ST + row * 128 + ((ci * 16) ^ ((row & 7) << 4)));
    }

    // --- ldmatrix per-lane address pieces
    const int warp_m = (wid & 3) * 32;
    const int warp_n = (wid >> 2) * 64;
    const int rA  = warp_m + (lane & 7) + ((lane >> 3) & 1) * 8;
    const int ksA = ((lane >> 4) & 1) * 16;
    const int xmA = (rA & 7) << 4;
    const int rB  = warp_n + (lane & 7) + ((lane >> 4) & 1) * 8;
    const int ksB = ((lane >> 3) & 1) * 16;
    const int xmB = (rB & 7) << 4;

    float acc[2][8][4];
    #pragma unroll
    for (int i = 0; i < 2; i++)
        #pragma unroll
        for (int j = 0; j < 8; j++)
            #pragma unroll
            for (int q = 0; q < 4; q++) acc[i][j][q] = 0.f;

    // prefetch stages 0,1
    #pragma unroll
    for (int s = 0; s < STAGES - 1; s++) {
        uint32_t bofs = sbase + s * STAGE_BYTES;
        #pragma unroll
        for (int i = 0; i < 2; i++) CP_ASYNC16(bofs + da[i], ga[i] + (size_t)s * 128);
        #pragma unroll
        for (int i = 0; i < 4; i++) CP_ASYNC16(bofs + db[i], gb[i] + (size_t)s * 128);
        CP_COMMIT();
    }

    for (int s = 0; s < S_TOT; s++) {
        CP_WAIT1();
        __syncthreads();

        if (s + 2 < S_TOT) {
            uint32_t bofs = sbase + ((s + 2) % STAGES) * STAGE_BYTES;
            size_t ko = (size_t)(s + 2) * 128;
            #pragma unroll
            for (int i = 0; i < 2; i++) CP_ASYNC16(bofs + da[i], ga[i] + ko);
            #pragma unroll
            for (int i = 0; i < 4; i++) CP_ASYNC16(bofs + db[i], gb[i] + ko);
        }
        CP_COMMIT();

        const uint32_t sA = sbase + (s % STAGES) * STAGE_BYTES;
        const uint32_t sB = sA + A_ST;

        #pragma unroll
        for (int ks = 0; ks < 4; ks++) {
            uint32_t a[2][4];
            #pragma unroll
            for (int i = 0; i < 2; i++) {
                uint32_t addr = sA + (rA + i * 16) * 128 + ((ks * 32 + ksA) ^ xmA);
                LDSM_X4(a[i][0], a[i][1], a[i][2], a[i][3], addr);
            }
            uint32_t b[4][4];
            #pragma unroll
            for (int blk = 0; blk < 4; blk++) {
                uint32_t addr = sB + (rB + blk * 16) * 128 + ((ks * 32 + ksB) ^ xmB);
                LDSM_X4(b[blk][0], b[blk][1], b[blk][2], b[blk][3], addr);
            }
            #pragma unroll
            for (int i = 0; i < 2; i++)
                #pragma unroll
                for (int jj = 0; jj < 8; jj++) {
                    int blk = jj >> 1, hi = (jj & 1) * 2;
                    MMA16816(acc[i][jj], a[i][0], a[i][1], a[i][2], a[i][3],
                             b[blk][hi], b[blk][hi + 1]);
                }
        }
    }

    // epilogue: direct stores + bias
    const int mrow = (int)m0 + warp_m + (lane >> 2);
    const int ncol = (int)n0 + warp_n + (lane & 3) * 2;
    #pragma unroll
    for (int i = 0; i < 2; i++) {
        #pragma unroll
        for (int jj = 0; jj < 8; jj++) {
            int col = ncol + jj * 8;
            float2 bv = *(const float2*)&bias[col];
            int r0 = mrow + i * 16, r1 = r0 + 8;
            float2 v0, v1;
            v0.x = acc[i][jj][0] + bv.x; v0.y = acc[i][jj][1] + bv.y;
            v1.x = acc[i][jj][2] + bv.x; v1.y = acc[i][jj][3] + bv.y;
            *(float2*)(out + (size_t)r0 * N_DIM + col) = v0;
            *(float2*)(out + (size_t)r1 * N_DIM + col) = v1;
        }
    }
}

// ---------------- launch ----------------
extern "C" void kernel_launch(void* const* d_in, const int* in_sizes, int n_in,
                              void* d_out, int out_size) {
    const float* x        = (const float*)d_in[0];
    const float* weight   = (const float*)d_in[1];
    const float* codebook = (const float*)d_in[2];
    const float* bias     = (const float*)d_in[3];
    float* out = (float*)d_out;

    pq_quantize<<<N_DIM, 256>>>(weight, codebook);
    x_convert<<<(M_DIM * K1 / 4) / 256, 256>>>(x);

    cudaFuncSetAttribute(pq_gemm_mma, cudaFuncAttributeMaxDynamicSharedMemorySize, SMEM_G);
    dim3 grid(N_DIM / BN2, M_DIM / BM2);   // (8, 64) = 512 CTAs
    pq_gemm_mma<<<grid, 512, SMEM_G>>>(bias, out);
}

// round 6
// speedup vs baseline: 2.4123x; 1.0156x over previous
#include <cuda_runtime.h>
#include <cuda_bf16.h>
#include <cstdint>

#define K1    4096
#define K3    8192           // stored K (2 segments; 3rd is aliased)
#define N_DIM 2048
#define M_DIM 8192
#define DGRP  8
#define KCB   256

// GEMM tiling
#define BM2    128
#define BN2    256
#define KC     64            // bf16 per stage => 128B rows
#define STAGES 4
#define S_TOT  192           // logical K = 12288 (3 segments of 64 stages)
#define A_ST   (BM2 * KC * 2)              // 16384
#define B_ST   (BN2 * KC * 2)              // 32768
#define STAGE_BYTES (A_ST + B_ST)          // 49152
#define SMEM_G (STAGES * STAGE_BYTES)      // 196608

__device__ __align__(256) __nv_bfloat16 g_xcat[(size_t)M_DIM * K3];  // [xhi|xlo]
__device__ __align__(256) __nv_bfloat16 g_wcat[(size_t)N_DIM * K3];  // [whi|wlo]

// ---------------- PTX helpers ----------------
__device__ __forceinline__ uint32_t smem_u32(const void* p) {
    uint32_t a;
    asm("{ .reg .u64 t; cvta.to.shared.u64 t, %1; cvt.u32.u64 %0, t; }" : "=r"(a) : "l"(p));
    return a;
}
#define CP_ASYNC16(dst, src) \
    asm volatile("cp.async.cg.shared.global [%0], [%1], 16;" :: "r"(dst), "l"(src))
#define CP_COMMIT() asm volatile("cp.async.commit_group;" ::: "memory")
#define CP_WAIT2()  asm volatile("cp.async.wait_group 2;" ::: "memory")

#define LDSM_X4(r0,r1,r2,r3,addr) \
    asm volatile("ldmatrix.sync.aligned.m8n8.x4.shared.b16 {%0,%1,%2,%3}, [%4];" \
                 : "=r"(r0), "=r"(r1), "=r"(r2), "=r"(r3) : "r"(addr))

#define MMA16816(d, a0,a1,a2,a3, b0,b1) \
    asm volatile("mma.sync.aligned.m16n8k16.row.col.f32.bf16.bf16.f32 " \
                 "{%0,%1,%2,%3},{%4,%5,%6,%7},{%8,%9},{%0,%1,%2,%3};" \
                 : "+f"((d)[0]), "+f"((d)[1]), "+f"((d)[2]), "+f"((d)[3]) \
                 : "r"(a0), "r"(a1), "r"(a2), "r"(a3), "r"(b0), "r"(b1))

// ---------------- Kernel 1: quantize weight + bf16 hi/lo split ----------------
__global__ __launch_bounds__(256)
void pq_quantize(const float* __restrict__ weight, const float* __restrict__ codebook) {
    __shared__ float cb[KCB * DGRP];
    __shared__ float cnorm_half[KCB];
    __shared__ float red[256];

    const int o = blockIdx.x, tid = threadIdx.x;
    for (int i = tid; i < KCB * DGRP; i += 256) cb[i] = codebook[i];
    __syncthreads();
    {
        float s = 0.f;
        #pragma unroll
        for (int j = 0; j < DGRP; j++) { float c = cb[tid * DGRP + j]; s = fmaf(c, c, s); }
        cnorm_half[tid] = 0.5f * s;
    }
    const float* wrow = weight + (size_t)o * K1;
    float m = 0.f;
    for (int i = tid; i < K1; i += 256) m = fmaxf(m, fabsf(wrow[i]));
    red[tid] = m;
    __syncthreads();
    for (int s = 128; s > 0; s >>= 1) { if (tid < s) red[tid] = fmaxf(red[tid], red[tid + s]); __syncthreads(); }
    const float scale = fmaxf(red[0], 1e-6f);
    const float inv = 1.f / scale;

    // two groups per thread: g0 = tid, g1 = tid + 256; shared codebook loads
    const float4* wrow4 = (const float4*)wrow;
    float4 ga0 = wrow4[tid * 2],         ga1 = wrow4[tid * 2 + 1];
    float4 gb0 = wrow4[(tid + 256) * 2], gb1 = wrow4[(tid + 256) * 2 + 1];
    float gva[DGRP] = {ga0.x*inv, ga0.y*inv, ga0.z*inv, ga0.w*inv,
                       ga1.x*inv, ga1.y*inv, ga1.z*inv, ga1.w*inv};
    float gvb[DGRP] = {gb0.x*inv, gb0.y*inv, gb0.z*inv, gb0.w*inv,
                       gb1.x*inv, gb1.y*inv, gb1.z*inv, gb1.w*inv};

    float best0 = 3.4e38f, best1 = 3.4e38f;
    int bi0 = 0, bi1 = 0;
    const float4* cb4 = (const float4*)cb;
    #pragma unroll 2
    for (int k = 0; k < KCB; k++) {
        float4 c0 = cb4[k * 2], c1 = cb4[k * 2 + 1];
        float cn = cnorm_half[k];
        float d0 = cn, d1 = cn;
        d0 = fmaf(-gva[0], c0.x, d0); d1 = fmaf(-gvb[0], c0.x, d1);
        d0 = fmaf(-gva[1], c0.y, d0); d1 = fmaf(-gvb[1], c0.y, d1);
        d0 = fmaf(-gva[2], c0.z, d0); d1 = fmaf(-gvb[2], c0.z, d1);
        d0 = fmaf(-gva[3], c0.w, d0); d1 = fmaf(-gvb[3], c0.w, d1);
        d0 = fmaf(-gva[4], c1.x, d0); d1 = fmaf(-gvb[4], c1.x, d1);
        d0 = fmaf(-gva[5], c1.y, d0); d1 = fmaf(-gvb[5], c1.y, d1);
        d0 = fmaf(-gva[6], c1.z, d0); d1 = fmaf(-gvb[6], c1.z, d1);
        d0 = fmaf(-gva[7], c1.w, d0); d1 = fmaf(-gvb[7], c1.w, d1);
        if (d0 < best0) { best0 = d0; bi0 = k; }
        if (d1 < best1) { best1 = d1; bi1 = k; }
    }

    __nv_bfloat16* wr = g_wcat + (size_t)o * K3;
    #pragma unroll
    for (int j = 0; j < DGRP; j++) {
        float w = cb[bi0 * DGRP + j] * scale;
        __nv_bfloat16 hi = __float2bfloat16(w);
        __nv_bfloat16 lo = __float2bfloat16(w - __bfloat162float(hi));
        int i = tid * DGRP + j;
        wr[i] = hi; wr[K1 + i] = lo;
    }
    #pragma unroll
    for (int j = 0; j < DGRP; j++) {
        float w = cb[bi1 * DGRP + j] * scale;
        __nv_bfloat16 hi = __float2bfloat16(w);
        __nv_bfloat16 lo = __float2bfloat16(w - __bfloat162float(hi));
        int i = (tid + 256) * DGRP + j;
        wr[i] = hi; wr[K1 + i] = lo;
    }
}

// ---------------- Kernel 2: x -> bf16 hi/lo ----------------
__global__ __launch_bounds__(256)
void x_convert(const float* __restrict__ x) {
    size_t idx = (size_t)blockIdx.x * 256 + threadIdx.x;   // one float4
    float4 v = ((const float4*)x)[idx];
    size_t m = idx >> 10;
    size_t kq = (idx & 1023) << 2;

    __nv_bfloat16 h0 = __float2bfloat16(v.x), h1 = __float2bfloat16(v.y);
    __nv_bfloat16 h2 = __float2bfloat16(v.z), h3 = __float2bfloat16(v.w);
    __nv_bfloat16 l0 = __float2bfloat16(v.x - __bfloat162float(h0));
    __nv_bfloat16 l1 = __float2bfloat16(v.y - __bfloat162float(h1));
    __nv_bfloat16 l2 = __float2bfloat16(v.z - __bfloat162float(h2));
    __nv_bfloat16 l3 = __float2bfloat16(v.w - __bfloat162float(h3));

    union { __nv_bfloat16 b[4]; uint2 u; } ph, pl;
    ph.b[0]=h0; ph.b[1]=h1; ph.b[2]=h2; ph.b[3]=h3;
    pl.b[0]=l0; pl.b[1]=l1; pl.b[2]=l2; pl.b[3]=l3;

    size_t base = m * K3 + kq;
    *(uint2*)(g_xcat + base)      = ph.u;   // x_hi
    *(uint2*)(g_xcat + base + K1) = pl.u;   // x_lo
}

// ---------------- Kernel 3: bf16 HMMA GEMM, 128x256 CTA, 4-stage cp.async ----------------
// Logical K = 12288 via segment aliasing:
//   A stage offset: s<128 ? s : s-128   (seg0=x_hi, seg1=x_lo, seg2->x_hi)
//   B stage offset: s<64  ? s : s-64    (seg0=w_hi, seg1->w_hi, seg2->w_lo)
__global__ __launch_bounds__(512, 1)
void pq_gemm_mma(const float* __restrict__ bias, float* __restrict__ out) {
    extern __shared__ char smem[];
    const uint32_t sbase = smem_u32(smem);
    const int tid  = threadIdx.x;
    const int wid  = tid >> 5;
    const int lane = tid & 31;

    const size_t m0 = (size_t)blockIdx.y * BM2;
    const size_t n0 = (size_t)blockIdx.x * BN2;
    const size_t gstride = (size_t)K3 * 2;   // row bytes

    const char* ga[2]; uint32_t da[2];
    #pragma unroll
    for (int i = 0; i < 2; i++) {
        int c = tid + 512 * i, row = c >> 3, ci = c & 7;
        ga[i] = (const char*)g_xcat + (m0 + row) * gstride + ci * 16;
        da[i] = (uint32_t)(row * 128 + ((ci * 16) ^ ((row & 7) << 4)));
    }
    const char* gb[4]; uint32_t db[4];
    #pragma unroll
    for (int i = 0; i < 4; i++) {
        int c = tid + 512 * i, row = c >> 3, ci = c & 7;
        gb[i] = (const char*)g_wcat + (n0 + row) * gstride + ci * 16;
        db[i] = (uint32_t)(A_ST + row * 128 + ((ci * 16) ^ ((row & 7) << 4)));
    }

    const int warp_m = (wid & 3) * 32;
    const int warp_n = (wid >> 2) * 64;
    const int rA  = warp_m + (lane & 7) + ((lane >> 3) & 1) * 8;
    const int ksA = ((lane >> 4) & 1) * 16;
    const int xmA = (rA & 7) << 4;
    const int rB  = warp_n + (lane & 7) + ((lane >> 4) & 1) * 8;
    const int ksB = ((lane >> 3) & 1) * 16;
    const int xmB = (rB & 7) << 4;

    float acc[2][8][4];
    #pragma unroll
    for (int i = 0; i < 2; i++)
        #pragma unroll
        for (int j = 0; j < 8; j++)
            #pragma unroll
            for (int q = 0; q < 4; q++) acc[i][j][q] = 0.f;

    // prefetch stages 0..2 (all within segment 0: offsets = s)
    #pragma unroll
    for (int s = 0; s < STAGES - 1; s++) {
        uint32_t bofs = sbase + s * STAGE_BYTES;
        #pragma unroll
        for (int i = 0; i < 2; i++) CP_ASYNC16(bofs + da[i], ga[i] + (size_t)s * 128);
        #pragma unroll
        for (int i = 0; i < 4; i++) CP_ASYNC16(bofs + db[i], gb[i] + (size_t)s * 128);
        CP_COMMIT();
    }

    for (int s = 0; s < S_TOT; s++) {
        CP_WAIT2();
        __syncthreads();

        if (s + 3 < S_TOT) {
            int s3 = s + 3;
            size_t koA = (size_t)(s3 < 128 ? s3 : s3 - 128) * 128;
            size_t koB = (size_t)(s3 < 64  ? s3 : s3 - 64 ) * 128;
            uint32_t bofs = sbase + (s3 & 3) * STAGE_BYTES;
            #pragma unroll
            for (int i = 0; i < 2; i++) CP_ASYNC16(bofs + da[i], ga[i] + koA);
            #pragma unroll
            for (int i = 0; i < 4; i++) CP_ASYNC16(bofs + db[i], gb[i] + koB);
        }
        CP_COMMIT();

        const uint32_t sA = sbase + (s & 3) * STAGE_BYTES;
        const uint32_t sB = sA + A_ST;

        #pragma unroll
        for (int ks = 0; ks < 4; ks++) {
            uint32_t a[2][4];
            #pragma unroll
            for (int i = 0; i < 2; i++) {
                uint32_t addr = sA + (rA + i * 16) * 128 + ((ks * 32 + ksA) ^ xmA);
                LDSM_X4(a[i][0], a[i][1], a[i][2], a[i][3], addr);
            }
            uint32_t b[4][4];
            #pragma unroll
            for (int blk = 0; blk < 4; blk++) {
                uint32_t addr = sB + (rB + blk * 16) * 128 + ((ks * 32 + ksB) ^ xmB);
                LDSM_X4(b[blk][0], b[blk][1], b[blk][2], b[blk][3], addr);
            }
            #pragma unroll
            for (int i = 0; i < 2; i++)
                #pragma unroll
                for (int jj = 0; jj < 8; jj++) {
                    int blk = jj >> 1, hi = (jj & 1) * 2;
                    MMA16816(acc[i][jj], a[i][0], a[i][1], a[i][2], a[i][3],
                             b[blk][hi], b[blk][hi + 1]);
                }
        }
    }

    // epilogue: direct stores + bias
    const int mrow = (int)m0 + warp_m + (lane >> 2);
    const int ncol = (int)n0 + warp_n + (lane & 3) * 2;
    #pragma unroll
    for (int i = 0; i < 2; i++) {
        #pragma unroll
        for (int jj = 0; jj < 8; jj++) {
            int col = ncol + jj * 8;
            float2 bv = *(const float2*)&bias[col];
            int r0 = mrow + i * 16, r1 = r0 + 8;
            float2 v0, v1;
            v0.x = acc[i][jj][0] + bv.x; v0.y = acc[i][jj][1] + bv.y;
            v1.x = acc[i][jj][2] + bv.x; v1.y = acc[i][jj][3] + bv.y;
            *(float2*)(out + (size_t)r0 * N_DIM + col) = v0;
            *(float2*)(out + (size_t)r1 * N_DIM + col) = v1;
        }
    }
}

// ---------------- launch ----------------
extern "C" void kernel_launch(void* const* d_in, const int* in_sizes, int n_in,
                              void* d_out, int out_size) {
    const float* x        = (const float*)d_in[0];
    const float* weight   = (const float*)d_in[1];
    const float* codebook = (const float*)d_in[2];
    const float* bias     = (const float*)d_in[3];
    float* out = (float*)d_out;

    pq_quantize<<<N_DIM, 256>>>(weight, codebook);
    x_convert<<<(M_DIM * K1 / 4) / 256, 256>>>(x);

    cudaFuncSetAttribute(pq_gemm_mma, cudaFuncAttributeMaxDynamicSharedMemorySize, SMEM_G);
    dim3 grid(N_DIM / BN2, M_DIM / BM2);   // (8, 64) = 512 CTAs
    pq_gemm_mma<<<grid, 512, SMEM_G>>>(bias, out);
}

// round 7
// speedup vs baseline: 2.7070x; 1.1222x over previous
#include <cuda_runtime.h>
#include <cuda_bf16.h>
#include <cstdint>

#define K1    4096
#define K3    8192           // stored K (2 segments; 3rd logical segment aliased)
#define N_DIM 2048
#define M_DIM 8192
#define DGRP  8
#define KCB   256

// GEMM tiling: 128x128 CTA, 256 threads (8 warps, 4x2 grid of 32x64 warp tiles)
#define BM2    128
#define BN2    128
#define KC     64            // bf16 per stage => 128B rows
#define STAGES 3
#define S_TOT  192           // logical K = 12288 (3 segments of 64 stages)
#define A_ST   (BM2 * KC * 2)              // 16384
#define B_ST   (BN2 * KC * 2)              // 16384
#define STAGE_BYTES (A_ST + B_ST)          // 32768
#define SMEM_G (STAGES * STAGE_BYTES)      // 98304 -> 2 CTAs/SM

__device__ __align__(256) __nv_bfloat16 g_xcat[(size_t)M_DIM * K3];  // [xhi|xlo]
__device__ __align__(256) __nv_bfloat16 g_wcat[(size_t)N_DIM * K3];  // [whi|wlo]

// ---------------- PTX helpers ----------------
__device__ __forceinline__ uint32_t smem_u32(const void* p) {
    uint32_t a;
    asm("{ .reg .u64 t; cvta.to.shared.u64 t, %1; cvt.u32.u64 %0, t; }" : "=r"(a) : "l"(p));
    return a;
}
#define CP_ASYNC16(dst, src) \
    asm volatile("cp.async.cg.shared.global [%0], [%1], 16;" :: "r"(dst), "l"(src))
#define CP_COMMIT() asm volatile("cp.async.commit_group;" ::: "memory")
#define CP_WAIT1()  asm volatile("cp.async.wait_group 1;" ::: "memory")

#define LDSM_X4(r0,r1,r2,r3,addr) \
    asm volatile("ldmatrix.sync.aligned.m8n8.x4.shared.b16 {%0,%1,%2,%3}, [%4];" \
                 : "=r"(r0), "=r"(r1), "=r"(r2), "=r"(r3) : "r"(addr))

#define MMA16816(d, a0,a1,a2,a3, b0,b1) \
    asm volatile("mma.sync.aligned.m16n8k16.row.col.f32.bf16.bf16.f32 " \
                 "{%0,%1,%2,%3},{%4,%5,%6,%7},{%8,%9},{%0,%1,%2,%3};" \
                 : "+f"((d)[0]), "+f"((d)[1]), "+f"((d)[2]), "+f"((d)[3]) \
                 : "r"(a0), "r"(a1), "r"(a2), "r"(a3), "r"(b0), "r"(b1))

// ---------------- Kernel 1: quantize weight + bf16 hi/lo split ----------------
__global__ __launch_bounds__(256)
void pq_quantize(const float* __restrict__ weight, const float* __restrict__ codebook) {
    __shared__ float cb[KCB * DGRP];
    __shared__ float cnorm_half[KCB];
    __shared__ float red[256];

    const int o = blockIdx.x, tid = threadIdx.x;
    for (int i = tid; i < KCB * DGRP; i += 256) cb[i] = codebook[i];
    __syncthreads();
    {
        float s = 0.f;
        #pragma unroll
        for (int j = 0; j < DGRP; j++) { float c = cb[tid * DGRP + j]; s = fmaf(c, c, s); }
        cnorm_half[tid] = 0.5f * s;
    }
    const float* wrow = weight + (size_t)o * K1;
    float m = 0.f;
    for (int i = tid; i < K1; i += 256) m = fmaxf(m, fabsf(wrow[i]));
    red[tid] = m;
    __syncthreads();
    for (int s = 128; s > 0; s >>= 1) { if (tid < s) red[tid] = fmaxf(red[tid], red[tid + s]); __syncthreads(); }
    const float scale = fmaxf(red[0], 1e-6f);
    const float inv = 1.f / scale;

    const float4* wrow4 = (const float4*)wrow;
    float4 ga0 = wrow4[tid * 2],         ga1 = wrow4[tid * 2 + 1];
    float4 gb0 = wrow4[(tid + 256) * 2], gb1 = wrow4[(tid + 256) * 2 + 1];
    float gva[DGRP] = {ga0.x*inv, ga0.y*inv, ga0.z*inv, ga0.w*inv,
                       ga1.x*inv, ga1.y*inv, ga1.z*inv, ga1.w*inv};
    float gvb[DGRP] = {gb0.x*inv, gb0.y*inv, gb0.z*inv, gb0.w*inv,
                       gb1.x*inv, gb1.y*inv, gb1.z*inv, gb1.w*inv};

    float best0 = 3.4e38f, best1 = 3.4e38f;
    int bi0 = 0, bi1 = 0;
    const float4* cb4 = (const float4*)cb;
    #pragma unroll 2
    for (int k = 0; k < KCB; k++) {
        float4 c0 = cb4[k * 2], c1 = cb4[k * 2 + 1];
        float cn = cnorm_half[k];
        float d0 = cn, d1 = cn;
        d0 = fmaf(-gva[0], c0.x, d0); d1 = fmaf(-gvb[0], c0.x, d1);
        d0 = fmaf(-gva[1], c0.y, d0); d1 = fmaf(-gvb[1], c0.y, d1);
        d0 = fmaf(-gva[2], c0.z, d0); d1 = fmaf(-gvb[2], c0.z, d1);
        d0 = fmaf(-gva[3], c0.w, d0); d1 = fmaf(-gvb[3], c0.w, d1);
        d0 = fmaf(-gva[4], c1.x, d0); d1 = fmaf(-gvb[4], c1.x, d1);
        d0 = fmaf(-gva[5], c1.y, d0); d1 = fmaf(-gvb[5], c1.y, d1);
        d0 = fmaf(-gva[6], c1.z, d0); d1 = fmaf(-gvb[6], c1.z, d1);
        d0 = fmaf(-gva[7], c1.w, d0); d1 = fmaf(-gvb[7], c1.w, d1);
        if (d0 < best0) { best0 = d0; bi0 = k; }
        if (d1 < best1) { best1 = d1; bi1 = k; }
    }

    __nv_bfloat16* wr = g_wcat + (size_t)o * K3;
    #pragma unroll
    for (int j = 0; j < DGRP; j++) {
        float w = cb[bi0 * DGRP + j] * scale;
        __nv_bfloat16 hi = __float2bfloat16(w);
        __nv_bfloat16 lo = __float2bfloat16(w - __bfloat162float(hi));
        int i = tid * DGRP + j;
        wr[i] = hi; wr[K1 + i] = lo;
    }
    #pragma unroll
    for (int j = 0; j < DGRP; j++) {
        float w = cb[bi1 * DGRP + j] * scale;
        __nv_bfloat16 hi = __float2bfloat16(w);
        __nv_bfloat16 lo = __float2bfloat16(w - __bfloat162float(hi));
        int i = (tid + 256) * DGRP + j;
        wr[i] = hi; wr[K1 + i] = lo;
    }
}

// ---------------- Kernel 2: x -> bf16 hi/lo ----------------
__global__ __launch_bounds__(256)
void x_convert(const float* __restrict__ x) {
    size_t idx = (size_t)blockIdx.x * 256 + threadIdx.x;   // one float4
    float4 v = ((const float4*)x)[idx];
    size_t m = idx >> 10;
    size_t kq = (idx & 1023) << 2;

    __nv_bfloat16 h0 = __float2bfloat16(v.x), h1 = __float2bfloat16(v.y);
    __nv_bfloat16 h2 = __float2bfloat16(v.z), h3 = __float2bfloat16(v.w);
    __nv_bfloat16 l0 = __float2bfloat16(v.x - __bfloat162float(h0));
    __nv_bfloat16 l1 = __float2bfloat16(v.y - __bfloat162float(h1));
    __nv_bfloat16 l2 = __float2bfloat16(v.z - __bfloat162float(h2));
    __nv_bfloat16 l3 = __float2bfloat16(v.w - __bfloat162float(h3));

    union { __nv_bfloat16 b[4]; uint2 u; } ph, pl;
    ph.b[0]=h0; ph.b[1]=h1; ph.b[2]=h2; ph.b[3]=h3;
    pl.b[0]=l0; pl.b[1]=l1; pl.b[2]=l2; pl.b[3]=l3;

    size_t base = m * K3 + kq;
    *(uint2*)(g_xcat + base)      = ph.u;   // x_hi
    *(uint2*)(g_xcat + base + K1) = pl.u;   // x_lo
}

// ---------------- Kernel 3: bf16 HMMA GEMM, 128x128 CTA, 3-stage, 2 CTAs/SM ----------------
// Logical K = 12288 via segment aliasing:
//   A stage offset: s<128 ? s : s-128   (seg0=x_hi, seg1=x_lo, seg2->x_hi)
//   B stage offset: s<64  ? s : s-64    (seg0=w_hi, seg1->w_hi, seg2->w_lo)
__global__ __launch_bounds__(256, 2)
void pq_gemm_mma(const float* __restrict__ bias, float* __restrict__ out) {
    extern __shared__ char smem[];
    const uint32_t sbase = smem_u32(smem);
    const int tid  = threadIdx.x;
    const int wid  = tid >> 5;
    const int lane = tid & 31;

    const size_t m0 = (size_t)blockIdx.y * BM2;
    const size_t n0 = (size_t)blockIdx.x * BN2;
    const size_t gstride = (size_t)K3 * 2;   // row bytes

    // cp.async: A 1024 16B-chunks (4/thread), B 1024 (4/thread)
    const char* ga[4]; uint32_t da[4];
    #pragma unroll
    for (int i = 0; i < 4; i++) {
        int c = tid + 256 * i, row = c >> 3, ci = c & 7;
        ga[i] = (const char*)g_xcat + (m0 + row) * gstride + ci * 16;
        da[i] = (uint32_t)(row * 128 + ((ci * 16) ^ ((row & 7) << 4)));
    }
    const char* gb[4]; uint32_t db[4];
    #pragma unroll
    for (int i = 0; i < 4; i++) {
        int c = tid + 256 * i, row = c >> 3, ci = c & 7;
        gb[i] = (const char*)g_wcat + (n0 + row) * gstride + ci * 16;
        db[i] = (uint32_t)(A_ST + row * 128 + ((ci * 16) ^ ((row & 7) << 4)));
    }

    // warp grid: 4 (M) x 2 (N); warp tile 32x64
    const int warp_m = (wid & 3) * 32;
    const int warp_n = (wid >> 2) * 64;
    const int rA  = warp_m + (lane & 7) + ((lane >> 3) & 1) * 8;
    const int ksA = ((lane >> 4) & 1) * 16;
    const int xmA = (rA & 7) << 4;
    const int rB  = warp_n + (lane & 7) + ((lane >> 4) & 1) * 8;
    const int ksB = ((lane >> 3) & 1) * 16;
    const int xmB = (rB & 7) << 4;

    float acc[2][8][4];
    #pragma unroll
    for (int i = 0; i < 2; i++)
        #pragma unroll
        for (int j = 0; j < 8; j++)
            #pragma unroll
            for (int q = 0; q < 4; q++) acc[i][j][q] = 0.f;

    // prefetch stages 0,1 (both in segment 0)
    #pragma unroll
    for (int s = 0; s < STAGES - 1; s++) {
        uint32_t bofs = sbase + s * STAGE_BYTES;
        #pragma unroll
        for (int i = 0; i < 4; i++) CP_ASYNC16(bofs + da[i], ga[i] + (size_t)s * 128);
        #pragma unroll
        for (int i = 0; i < 4; i++) CP_ASYNC16(bofs + db[i], gb[i] + (size_t)s * 128);
        CP_COMMIT();
    }

    for (int s = 0; s < S_TOT; s++) {
        CP_WAIT1();
        __syncthreads();

        if (s + 2 < S_TOT) {
            int s2 = s + 2;
            size_t koA = (size_t)(s2 < 128 ? s2 : s2 - 128) * 128;
            size_t koB = (size_t)(s2 < 64  ? s2 : s2 - 64 ) * 128;
            uint32_t bofs = sbase + (s2 % STAGES) * STAGE_BYTES;
            #pragma unroll
            for (int i = 0; i < 4; i++) CP_ASYNC16(bofs + da[i], ga[i] + koA);
            #pragma unroll
            for (int i = 0; i < 4; i++) CP_ASYNC16(bofs + db[i], gb[i] + koB);
        }
        CP_COMMIT();

        const uint32_t sA = sbase + (s % STAGES) * STAGE_BYTES;
        const uint32_t sB = sA + A_ST;

        #pragma unroll
        for (int ks = 0; ks < 4; ks++) {
            uint32_t a[2][4];
            #pragma unroll
            for (int i = 0; i < 2; i++) {
                uint32_t addr = sA + (rA + i * 16) * 128 + ((ks * 32 + ksA) ^ xmA);
                LDSM_X4(a[i][0], a[i][1], a[i][2], a[i][3], addr);
            }
            uint32_t b[4][4];
            #pragma unroll
            for (int blk = 0; blk < 4; blk++) {
                uint32_t addr = sB + (rB + blk * 16) * 128 + ((ks * 32 + ksB) ^ xmB);
                LDSM_X4(b[blk][0], b[blk][1], b[blk][2], b[blk][3], addr);
            }
            #pragma unroll
            for (int i = 0; i < 2; i++)
                #pragma unroll
                for (int jj = 0; jj < 8; jj++) {
                    int blk = jj >> 1, hi = (jj & 1) * 2;
                    MMA16816(acc[i][jj], a[i][0], a[i][1], a[i][2], a[i][3],
                             b[blk][hi], b[blk][hi + 1]);
                }
        }
    }

    // epilogue: direct stores + bias
    const int mrow = (int)m0 + warp_m + (lane >> 2);
    const int ncol = (int)n0 + warp_n + (lane & 3) * 2;
    #pragma unroll
    for (int i = 0; i < 2; i++) {
        #pragma unroll
        for (int jj = 0; jj < 8; jj++) {
            int col = ncol + jj * 8;
            float2 bv = *(const float2*)&bias[col];
            int r0 = mrow + i * 16, r1 = r0 + 8;
            float2 v0, v1;
            v0.x = acc[i][jj][0] + bv.x; v0.y = acc[i][jj][1] + bv.y;
            v1.x = acc[i][jj][2] + bv.x; v1.y = acc[i][jj][3] + bv.y;
            *(float2*)(out + (size_t)r0 * N_DIM + col) = v0;
            *(float2*)(out + (size_t)r1 * N_DIM + col) = v1;
        }
    }
}

// ---------------- launch ----------------
extern "C" void kernel_launch(void* const* d_in, const int* in_sizes, int n_in,
                              void* d_out, int out_size) {
    const float* x        = (const float*)d_in[0];
    const float* weight   = (const float*)d_in[1];
    const float* codebook = (const float*)d_in[2];
    const float* bias     = (const float*)d_in[3];
    float* out = (float*)d_out;

    pq_quantize<<<N_DIM, 256>>>(weight, codebook);
    x_convert<<<(M_DIM * K1 / 4) / 256, 256>>>(x);

    cudaFuncSetAttribute(pq_gemm_mma, cudaFuncAttributeMaxDynamicSharedMemorySize, SMEM_G);
    dim3 grid(N_DIM / BN2, M_DIM / BM2);   // (16, 64) = 1024 CTAs
    pq_gemm_mma<<<grid, 256, SMEM_G>>>(bias, out);
}

// round 8
// speedup vs baseline: 2.9114x; 1.0755x over previous
#include <cuda_runtime.h>
#include <cuda_bf16.h>
#include <cstdint>

#define K1    4096
#define K3    8192           // stored K: [hi | lo] segments
#define N_DIM 2048
#define M_DIM 8192
#define DGRP  8
#define KCB   256

// GEMM: 128x128 CTA, 256 threads (8 warps, 4x2 grid of 32x64 warp tiles)
#define BM2    128
#define BN2    128
#define A_TILE 16384                       // 128 rows x 128 B
#define PH_A_STAGE (3 * A_TILE)            // xh + xl + wh = 49152
#define PH_B_STAGE (2 * A_TILE)            // xh + wl      = 32768
#define SMEM_G 98304                       // 2 x phaseA  ==  3 x phaseB ; 2 CTAs/SM

__device__ __align__(256) __nv_bfloat16 g_xcat[(size_t)M_DIM * K3];  // [xhi|xlo]
__device__ __align__(256) __nv_bfloat16 g_wcat[(size_t)N_DIM * K3];  // [whi|wlo]

// ---------------- PTX helpers ----------------
__device__ __forceinline__ uint32_t smem_u32(const void* p) {
    uint32_t a;
    asm("{ .reg .u64 t; cvta.to.shared.u64 t, %1; cvt.u32.u64 %0, t; }" : "=r"(a) : "l"(p));
    return a;
}
#define CP_ASYNC16(dst, src) \
    asm volatile("cp.async.cg.shared.global [%0], [%1], 16;" :: "r"(dst), "l"(src))
#define CP_COMMIT() asm volatile("cp.async.commit_group;" ::: "memory")
#define CP_WAIT1()  asm volatile("cp.async.wait_group 1;" ::: "memory")
#define CP_WAIT0()  asm volatile("cp.async.wait_group 0;" ::: "memory")

#define LDSM_X4(r0,r1,r2,r3,addr) \
    asm volatile("ldmatrix.sync.aligned.m8n8.x4.shared.b16 {%0,%1,%2,%3}, [%4];" \
                 : "=r"(r0), "=r"(r1), "=r"(r2), "=r"(r3) : "r"(addr))

#define MMA16816(d, a0,a1,a2,a3, b0,b1) \
    asm volatile("mma.sync.aligned.m16n8k16.row.col.f32.bf16.bf16.f32 " \
                 "{%0,%1,%2,%3},{%4,%5,%6,%7},{%8,%9},{%0,%1,%2,%3};" \
                 : "+f"((d)[0]), "+f"((d)[1]), "+f"((d)[2]), "+f"((d)[3]) \
                 : "r"(a0), "r"(a1), "r"(a2), "r"(a3), "r"(b0), "r"(b1))

// ---------------- Kernel 1: quantize weight + bf16 hi/lo split ----------------
__global__ __launch_bounds__(256)
void pq_quantize(const float* __restrict__ weight, const float* __restrict__ codebook) {
    __shared__ float cb[KCB * DGRP];
    __shared__ float cnorm_half[KCB];
    __shared__ float red[256];

    const int o = blockIdx.x, tid = threadIdx.x;
    for (int i = tid; i < KCB * DGRP; i += 256) cb[i] = codebook[i];
    __syncthreads();
    {
        float s = 0.f;
        #pragma unroll
        for (int j = 0; j < DGRP; j++) { float c = cb[tid * DGRP + j]; s = fmaf(c, c, s); }
        cnorm_half[tid] = 0.5f * s;
    }
    const float* wrow = weight + (size_t)o * K1;
    float m = 0.f;
    for (int i = tid; i < K1; i += 256) m = fmaxf(m, fabsf(wrow[i]));
    red[tid] = m;
    __syncthreads();
    for (int s = 128; s > 0; s >>= 1) { if (tid < s) red[tid] = fmaxf(red[tid], red[tid + s]); __syncthreads(); }
    const float scale = fmaxf(red[0], 1e-6f);
    const float inv = 1.f / scale;

    const float4* wrow4 = (const float4*)wrow;
    float4 ga0 = wrow4[tid * 2],         ga1 = wrow4[tid * 2 + 1];
    float4 gb0 = wrow4[(tid + 256) * 2], gb1 = wrow4[(tid + 256) * 2 + 1];
    float gva[DGRP] = {ga0.x*inv, ga0.y*inv, ga0.z*inv, ga0.w*inv,
                       ga1.x*inv, ga1.y*inv, ga1.z*inv, ga1.w*inv};
    float gvb[DGRP] = {gb0.x*inv, gb0.y*inv, gb0.z*inv, gb0.w*inv,
                       gb1.x*inv, gb1.y*inv, gb1.z*inv, gb1.w*inv};

    float best0 = 3.4e38f, best1 = 3.4e38f;
    int bi0 = 0, bi1 = 0;
    const float4* cb4 = (const float4*)cb;
    #pragma unroll 2
    for (int k = 0; k < KCB; k++) {
        float4 c0 = cb4[k * 2], c1 = cb4[k * 2 + 1];
        float cn = cnorm_half[k];
        float d0 = cn, d1 = cn;
        d0 = fmaf(-gva[0], c0.x, d0); d1 = fmaf(-gvb[0], c0.x, d1);
        d0 = fmaf(-gva[1], c0.y, d0); d1 = fmaf(-gvb[1], c0.y, d1);
        d0 = fmaf(-gva[2], c0.z, d0); d1 = fmaf(-gvb[2], c0.z, d1);
        d0 = fmaf(-gva[3], c0.w, d0); d1 = fmaf(-gvb[3], c0.w, d1);
        d0 = fmaf(-gva[4], c1.x, d0); d1 = fmaf(-gvb[4], c1.x, d1);
        d0 = fmaf(-gva[5], c1.y, d0); d1 = fmaf(-gvb[5], c1.y, d1);
        d0 = fmaf(-gva[6], c1.z, d0); d1 = fmaf(-gvb[6], c1.z, d1);
        d0 = fmaf(-gva[7], c1.w, d0); d1 = fmaf(-gvb[7], c1.w, d1);
        if (d0 < best0) { best0 = d0; bi0 = k; }
        if (d1 < best1) { best1 = d1; bi1 = k; }
    }

    __nv_bfloat16* wr = g_wcat + (size_t)o * K3;
    #pragma unroll
    for (int j = 0; j < DGRP; j++) {
        float w = cb[bi0 * DGRP + j] * scale;
        __nv_bfloat16 hi = __float2bfloat16(w);
        __nv_bfloat16 lo = __float2bfloat16(w - __bfloat162float(hi));
        int i = tid * DGRP + j;
        wr[i] = hi; wr[K1 + i] = lo;
    }
    #pragma unroll
    for (int j = 0; j < DGRP; j++) {
        float w = cb[bi1 * DGRP + j] * scale;
        __nv_bfloat16 hi = __float2bfloat16(w);
        __nv_bfloat16 lo = __float2bfloat16(w - __bfloat162float(hi));
        int i = (tid + 256) * DGRP + j;
        wr[i] = hi; wr[K1 + i] = lo;
    }
}

// ---------------- Kernel 2: x -> bf16 hi/lo ----------------
__global__ __launch_bounds__(256)
void x_convert(const float* __restrict__ x) {
    size_t idx = (size_t)blockIdx.x * 256 + threadIdx.x;   // one float4
    float4 v = ((const float4*)x)[idx];
    size_t m = idx >> 10;
    size_t kq = (idx & 1023) << 2;

    __nv_bfloat16 h0 = __float2bfloat16(v.x), h1 = __float2bfloat16(v.y);
    __nv_bfloat16 h2 = __float2bfloat16(v.z), h3 = __float2bfloat16(v.w);
    __nv_bfloat16 l0 = __float2bfloat16(v.x - __bfloat162float(h0));
    __nv_bfloat16 l1 = __float2bfloat16(v.y - __bfloat162float(h1));
    __nv_bfloat16 l2 = __float2bfloat16(v.z - __bfloat162float(h2));
    __nv_bfloat16 l3 = __float2bfloat16(v.w - __bfloat162float(h3));

    union { __nv_bfloat16 b[4]; uint2 u; } ph, pl;
    ph.b[0]=h0; ph.b[1]=h1; ph.b[2]=h2; ph.b[3]=h3;
    pl.b[0]=l0; pl.b[1]=l1; pl.b[2]=l2; pl.b[3]=l3;

    size_t base = m * K3 + kq;
    *(uint2*)(g_xcat + base)      = ph.u;   // x_hi
    *(uint2*)(g_xcat + base + K1) = pl.u;   // x_lo
}

// ---------------- Kernel 3: bf16 HMMA GEMM, two-phase operand-reuse ----------------
// Phase A (64 stages, k over [0,4096)): stage = {xh, xl, wh}; acc += xh*wh + xl*wh
//   (wh registers loaded once, used for both products)
// Phase B (64 stages):                  stage = {xh, wl};     acc += xh*wl
__global__ __launch_bounds__(256, 2)
void pq_gemm_mma(const float* __restrict__ bias, float* __restrict__ out) {
    extern __shared__ char smem[];
    const uint32_t sbase = smem_u32(smem);
    const int tid  = threadIdx.x;
    const int wid  = tid >> 5;
    const int lane = tid & 31;

    const size_t m0 = (size_t)blockIdx.y * BM2;
    const size_t n0 = (size_t)blockIdx.x * BN2;
    const size_t gstride = (size_t)K3 * 2;   // row bytes

    // per-thread 16B-chunk mapping within a 16KB tile (4 chunks/thread)
    const char* ga[4]; const char* gb[4]; uint32_t chA[4], chB[4];
    #pragma unroll
    for (int i = 0; i < 4; i++) {
        int c = tid + 256 * i, row = c >> 3, ci = c & 7;
        uint32_t off = (uint32_t)(row * 128 + ((ci * 16) ^ ((row & 7) << 4)));
        ga[i] = (const char*)g_xcat + (m0 + row) * gstride + ci * 16;
        gb[i] = (const char*)g_wcat + (n0 + row) * gstride + ci * 16;
        chA[i] = off; chB[i] = off;
    }

    // warp grid: 4 (M) x 2 (N); warp tile 32x64
    const int warp_m = (wid & 3) * 32;
    const int warp_n = (wid >> 2) * 64;
    const int rA  = warp_m + (lane & 7) + ((lane >> 3) & 1) * 8;
    const int ksA = ((lane >> 4) & 1) * 16;
    const int xmA = (rA & 7) << 4;
    const int rB  = warp_n + (lane & 7) + ((lane >> 4) & 1) * 8;
    const int ksB = ((lane >> 3) & 1) * 16;
    const int xmB = (rB & 7) << 4;

    float acc[2][8][4];
    #pragma unroll
    for (int i = 0; i < 2; i++)
        #pragma unroll
        for (int j = 0; j < 8; j++)
            #pragma unroll
            for (int q = 0; q < 4; q++) acc[i][j][q] = 0.f;

    // ================= Phase A: 2-stage pipeline, 48KB stages =================
    // prefetch stage 0
    {
        uint32_t bofs = sbase;
        #pragma unroll
        for (int i = 0; i < 4; i++) {
            CP_ASYNC16(bofs + chA[i],              ga[i]);            // xh
            CP_ASYNC16(bofs + A_TILE + chA[i],     ga[i] + 8192);     // xl
            CP_ASYNC16(bofs + 2*A_TILE + chB[i],   gb[i]);            // wh
        }
        CP_COMMIT();
    }

    for (int s = 0; s < 64; s++) {
        if (s + 1 < 64) {
            uint32_t bofs = sbase + ((s + 1) & 1) * PH_A_STAGE;
            size_t ko = (size_t)(s + 1) * 128;
            #pragma unroll
            for (int i = 0; i < 4; i++) {
                CP_ASYNC16(bofs + chA[i],            ga[i] + ko);
                CP_ASYNC16(bofs + A_TILE + chA[i],   ga[i] + ko + 8192);
                CP_ASYNC16(bofs + 2*A_TILE + chB[i], gb[i] + ko);
            }
        }
        CP_COMMIT();
        CP_WAIT1();
        __syncthreads();

        const uint32_t sXH = sbase + (s & 1) * PH_A_STAGE;
        const uint32_t sXL = sXH + A_TILE;
        const uint32_t sWH = sXH + 2 * A_TILE;

        #pragma unroll
        for (int ks = 0; ks < 4; ks++) {
            uint32_t ah[2][4], al[2][4];
            #pragma unroll
            for (int i = 0; i < 2; i++) {
                uint32_t aoff = (rA + i * 16) * 128 + ((ks * 32 + ksA) ^ xmA);
                LDSM_X4(ah[i][0], ah[i][1], ah[i][2], ah[i][3], sXH + aoff);
                LDSM_X4(al[i][0], al[i][1], al[i][2], al[i][3], sXL + aoff);
            }
            uint32_t b[4][4];
            #pragma unroll
            for (int blk = 0; blk < 4; blk++) {
                uint32_t boff = (rB + blk * 16) * 128 + ((ks * 32 + ksB) ^ xmB);
                LDSM_X4(b[blk][0], b[blk][1], b[blk][2], b[blk][3], sWH + boff);
            }
            #pragma unroll
            for (int i = 0; i < 2; i++)
                #pragma unroll
                for (int jj = 0; jj < 8; jj++) {
                    int blk = jj >> 1, hb = (jj & 1) * 2;
                    MMA16816(acc[i][jj], ah[i][0], ah[i][1], ah[i][2], ah[i][3],
                             b[blk][hb], b[blk][hb + 1]);
                    MMA16816(acc[i][jj], al[i][0], al[i][1], al[i][2], al[i][3],
                             b[blk][hb], b[blk][hb + 1]);
                }
        }
        __syncthreads();   // protect buffer before next iteration's prefetch
    }

    // ================= Phase transition: drain, then warm Phase B =================
    CP_WAIT0();
    __syncthreads();
    #pragma unroll
    for (int s = 0; s < 2; s++) {
        uint32_t bofs = sbase + s * PH_B_STAGE;
        size_t ko = (size_t)s * 128;
        #pragma unroll
        for (int i = 0; i < 4; i++) {
            CP_ASYNC16(bofs + chA[i],          ga[i] + ko);          // xh
            CP_ASYNC16(bofs + A_TILE + chB[i], gb[i] + ko + 8192);   // wl
        }
        CP_COMMIT();
    }

    // ================= Phase B: 3-stage pipeline, 32KB stages =================
    for (int s = 0; s < 64; s++) {
        CP_WAIT1();
        __syncthreads();

        if (s + 2 < 64) {
            uint32_t bofs = sbase + ((s + 2) % 3) * PH_B_STAGE;
            size_t ko = (size_t)(s + 2) * 128;
            #pragma unroll
            for (int i = 0; i < 4; i++) {
                CP_ASYNC16(bofs + chA[i],          ga[i] + ko);
                CP_ASYNC16(bofs + A_TILE + chB[i], gb[i] + ko + 8192);
            }
        }
        CP_COMMIT();

        const uint32_t sA = sbase + (s % 3) * PH_B_STAGE;
        const uint32_t sB = sA + A_TILE;

        #pragma unroll
        for (int ks = 0; ks < 4; ks++) {
            uint32_t a[2][4];
            #pragma unroll
            for (int i = 0; i < 2; i++) {
                uint32_t aoff = (rA + i * 16) * 128 + ((ks * 32 + ksA) ^ xmA);
                LDSM_X4(a[i][0], a[i][1], a[i][2], a[i][3], sA + aoff);
            }
            uint32_t b[4][4];
            #pragma unroll
            for (int blk = 0; blk < 4; blk++) {
                uint32_t boff = (rB + blk * 16) * 128 + ((ks * 32 + ksB) ^ xmB);
                LDSM_X4(b[blk][0], b[blk][1], b[blk][2], b[blk][3], sB + boff);
            }
            #pragma unroll
            for (int i = 0; i < 2; i++)
                #pragma unroll
                for (int jj = 0; jj < 8; jj++) {
                    int blk = jj >> 1, hb = (jj & 1) * 2;
                    MMA16816(acc[i][jj], a[i][0], a[i][1], a[i][2], a[i][3],
                             b[blk][hb], b[blk][hb + 1]);
                }
        }
        __syncthreads();   // buffer reuse guard (3-stage: s+2 writes (s+2)%3 != s%3, but
                           // next iter's writes target (s+3)%3 == s%3 — guard before that)
    }

    // epilogue: direct stores + bias
    const int mrow = (int)m0 + warp_m + (lane >> 2);
    const int ncol = (int)n0 + warp_n + (lane & 3) * 2;
    #pragma unroll
    for (int i = 0; i < 2; i++) {
        #pragma unroll
        for (int jj = 0; jj < 8; jj++) {
            int col = ncol + jj * 8;
            float2 bv = *(const float2*)&bias[col];
            int r0 = mrow + i * 16, r1 = r0 + 8;
            float2 v0, v1;
            v0.x = acc[i][jj][0] + bv.x; v0.y = acc[i][jj][1] + bv.y;
            v1.x = acc[i][jj][2] + bv.x; v1.y = acc[i][jj][3] + bv.y;
            *(float2*)(out + (size_t)r0 * N_DIM + col) = v0;
            *(float2*)(out + (size_t)r1 * N_DIM + col) = v1;
        }
    }
}

// ---------------- launch ----------------
extern "C" void kernel_launch(void* const* d_in, const int* in_sizes, int n_in,
                              void* d_out, int out_size) {
    const float* x        = (const float*)d_in[0];
    const float* weight   = (const float*)d_in[1];
    const float* codebook = (const float*)d_in[2];
    const float* bias     = (const float*)d_in[3];
    float* out = (float*)d_out;

    pq_quantize<<<N_DIM, 256>>>(weight, codebook);
    x_convert<<<(M_DIM * K1 / 4) / 256, 256>>>(x);

    cudaFuncSetAttribute(pq_gemm_mma, cudaFuncAttributeMaxDynamicSharedMemorySize, SMEM_G);
    dim3 grid(N_DIM / BN2, M_DIM / BM2);   // (16, 64) = 1024 CTAs
    pq_gemm_mma<<<grid, 256, SMEM_G>>>(bias, out);
}